// round 6
// baseline (speedup 1.0000x reference)
#include <cuda_runtime.h>
#include <math.h>

#define Nn 50000
#define Ee 1600000
#define Gg 64
#define NB 49   // ceil(Nn/1024)

// ---------------- device scratch ----------------
__device__ float g_h[Nn*64];
__device__ float g_Q[Nn*64];
__device__ float g_K[Nn*64];
__device__ float g_V[Nn*64];
__device__ float g_S[Nn*64];
__device__ float g_U[Nn*64];
__device__ int   g_deg[Nn];
__device__ int   g_rowptr[Nn+1];
__device__ int   g_cursor[Nn];
__device__ int   g_bsum[64];
__device__ int2  g_perm[Ee];        // {src, edge id} CSR(dst)-ordered
__device__ int   g_srcperm[Ee];     // src only, CSR-ordered (written by gatherE)
__device__ float g_eaperm[Ee*16];   // eattr permuted into CSR order
__device__ float g_pool[Gg*64];
__device__ int   g_cnt[Gg];

// ---------------- zero degree ----------------
__global__ void zero_kernel() {
    int i = blockIdx.x * blockDim.x + threadIdx.x;
    for (; i < Nn; i += gridDim.x * blockDim.x) g_deg[i] = 0;
}

// ---------------- degree histogram ----------------
__global__ void hist_kernel(const int* __restrict__ dst) {
    int e = blockIdx.x * blockDim.x + threadIdx.x;
    if (e < Ee) atomicAdd(&g_deg[dst[e]], 1);
}

// ---------------- scan A: block-local exclusive scan (+ zero pool) ----------------
__global__ void scanA_kernel() {
    __shared__ int sh[1024];
    int tid = threadIdx.x;
    int i = blockIdx.x * 1024 + tid;
    if (blockIdx.x == 0) {   // fold pool/cnt zeroing here
        if (tid < Gg) g_cnt[tid] = 0;
        for (int j = tid; j < Gg*64; j += 1024) g_pool[j] = 0.f;
    }
    int v = (i < Nn) ? g_deg[i] : 0;
    sh[tid] = v;
    __syncthreads();
    for (int off = 1; off < 1024; off <<= 1) {
        int t = (tid >= off) ? sh[tid - off] : 0;
        __syncthreads();
        sh[tid] += t;
        __syncthreads();
    }
    if (i < Nn) g_rowptr[i] = sh[tid] - v;
    if (tid == 1023) g_bsum[blockIdx.x] = sh[1023];
}

// ---------------- scan B+C fused: add carry of previous blocks ----------------
__global__ void scanBC_kernel() {
    __shared__ int sh[64];
    __shared__ int carry;
    int t = threadIdx.x;
    if (t < 64) sh[t] = (t < blockIdx.x && t < NB) ? g_bsum[t] : 0;
    __syncthreads();
    if (t == 0) { int s = 0; for (int j = 0; j < 64; j++) s += sh[j]; carry = s; }
    __syncthreads();
    int i = blockIdx.x * 1024 + t;
    if (i < Nn) { int r = g_rowptr[i] + carry; g_rowptr[i] = r; g_cursor[i] = r; }
    if (i == 0) g_rowptr[Nn] = Ee;
}

// ---------------- scatter {src, edge id} into CSR(dst) order ----------------
__global__ void scatter_kernel(const int* __restrict__ src,
                               const int* __restrict__ dst) {
    int e = blockIdx.x * blockDim.x + threadIdx.x;
    if (e >= Ee) return;
    int d = dst[e];
    int p = atomicAdd(&g_cursor[d], 1);
    g_perm[p] = make_int2(src[e], e);
}

// ---------------- gather eattr into CSR order (coalesced writes) ----------------
__global__ void gatherE_kernel(const float* __restrict__ eattr) {
    int t = blockIdx.x * blockDim.x + threadIdx.x;
    if (t >= Ee * 4) return;
    int slot = t >> 2, part = t & 3;
    int2 p = g_perm[slot];
    float4 v = *(const float4*)(eattr + (size_t)p.y * 16 + part * 4);
    *(float4*)(g_eaperm + (size_t)slot * 16 + part * 4) = v;
    if (part == 0) g_srcperm[slot] = p.x;
}

// ---------------- input MLP: h = relu(x @ Wn + bn), register-tiled ----------------
__global__ __launch_bounds__(256) void node_in_kernel(const float* __restrict__ x,
                                                      const float* __restrict__ Wn,
                                                      const float* __restrict__ bn) {
    __shared__ __align__(16) float xs[32*36];
    __shared__ __align__(16) float Wns[32*64];
    __shared__ float bns[64];
    int t = threadIdx.x;
    for (int i = t; i < 32*64; i += 256) Wns[i] = Wn[i];
    if (t < 64) bns[t] = bn[t];
    int base = blockIdx.x * 32;
    {
        int r = t >> 3, seg = t & 7;        // seg*4 in [0,32)
        int node = base + r;
        float4 a = make_float4(0,0,0,0);
        if (node < Nn) a = *(const float4*)(x + (size_t)node*32 + seg*4);
        *(float4*)&xs[r*36 + seg*4] = a;
    }
    __syncthreads();
    int n0 = t >> 3;
    int c8 = (t & 7) * 8;
    float acc[8];
    #pragma unroll
    for (int j = 0; j < 8; j++) acc[j] = bns[c8 + j];
    #pragma unroll 4
    for (int k = 0; k < 32; k++) {
        float rh = xs[n0*36 + k];
        float4 w0 = *(float4*)&Wns[k*64 + c8];
        float4 w1 = *(float4*)&Wns[k*64 + c8 + 4];
        acc[0] = fmaf(rh, w0.x, acc[0]); acc[1] = fmaf(rh, w0.y, acc[1]);
        acc[2] = fmaf(rh, w0.z, acc[2]); acc[3] = fmaf(rh, w0.w, acc[3]);
        acc[4] = fmaf(rh, w1.x, acc[4]); acc[5] = fmaf(rh, w1.y, acc[5]);
        acc[6] = fmaf(rh, w1.z, acc[6]); acc[7] = fmaf(rh, w1.w, acc[7]);
    }
    int node = base + n0;
    if (node < Nn) {
        float4 o0 = make_float4(fmaxf(acc[0],0.f), fmaxf(acc[1],0.f), fmaxf(acc[2],0.f), fmaxf(acc[3],0.f));
        float4 o1 = make_float4(fmaxf(acc[4],0.f), fmaxf(acc[5],0.f), fmaxf(acc[6],0.f), fmaxf(acc[7],0.f));
        *(float4*)(g_h + (size_t)node*64 + c8)     = o0;
        *(float4*)(g_h + (size_t)node*64 + c8 + 4) = o1;
    }
}

// ---------------- Q,K,U fused, register-tiled ----------------
__global__ __launch_bounds__(256) void qku_kernel(const float* __restrict__ Wq, const float* __restrict__ bq,
                                                  const float* __restrict__ Wk, const float* __restrict__ bk,
                                                  const float* __restrict__ Wel) {
    __shared__ __align__(16) float hs[32*68];
    __shared__ __align__(16) float WQs[4096];
    __shared__ __align__(16) float WKs[4096];
    __shared__ float WEsT[1024];   // WEsT[ch*16+j] = We[j][ch]
    __shared__ float bQs[64], bKs[64];
    int t = threadIdx.x;
    for (int i = t; i < 4096; i += 256) { WQs[i] = Wq[i]; WKs[i] = Wk[i]; }
    for (int i = t; i < 1024; i += 256) { int ch = i >> 4, j = i & 15; WEsT[i] = Wel[j*64 + ch]; }
    if (t < 64) { bQs[t] = bq[t]; bKs[t] = bk[t]; }
    int base = blockIdx.x * 32;
    {
        int r = t >> 3, seg = t & 7;
        int node = base + r;
        const float* hp = g_h + (size_t)node*64 + seg*8;
        float4 a = make_float4(0,0,0,0), b = a;
        if (node < Nn) { a = *(const float4*)hp; b = *(const float4*)(hp + 4); }
        *(float4*)&hs[r*68 + seg*8]     = a;
        *(float4*)&hs[r*68 + seg*8 + 4] = b;
    }
    __syncthreads();
    int n0 = t >> 3;
    int c8 = (t & 7) * 8;
    float aq[8], ak[8];
    #pragma unroll
    for (int j = 0; j < 8; j++) { aq[j] = bQs[c8+j]; ak[j] = bKs[c8+j]; }
    #pragma unroll 4
    for (int k = 0; k < 64; k++) {
        float rh = hs[n0*68 + k];
        float4 q0 = *(float4*)&WQs[k*64 + c8];
        float4 q1 = *(float4*)&WQs[k*64 + c8 + 4];
        float4 k0 = *(float4*)&WKs[k*64 + c8];
        float4 k1 = *(float4*)&WKs[k*64 + c8 + 4];
        aq[0]=fmaf(rh,q0.x,aq[0]); aq[1]=fmaf(rh,q0.y,aq[1]); aq[2]=fmaf(rh,q0.z,aq[2]); aq[3]=fmaf(rh,q0.w,aq[3]);
        aq[4]=fmaf(rh,q1.x,aq[4]); aq[5]=fmaf(rh,q1.y,aq[5]); aq[6]=fmaf(rh,q1.z,aq[6]); aq[7]=fmaf(rh,q1.w,aq[7]);
        ak[0]=fmaf(rh,k0.x,ak[0]); ak[1]=fmaf(rh,k0.y,ak[1]); ak[2]=fmaf(rh,k0.z,ak[2]); ak[3]=fmaf(rh,k0.w,ak[3]);
        ak[4]=fmaf(rh,k1.x,ak[4]); ak[5]=fmaf(rh,k1.y,ak[5]); ak[6]=fmaf(rh,k1.z,ak[6]); ak[7]=fmaf(rh,k1.w,ak[7]);
    }
    int node = base + n0;
    bool valid = node < Nn;
    if (valid) {
        *(float4*)(g_Q + (size_t)node*64 + c8)     = make_float4(aq[0],aq[1],aq[2],aq[3]);
        *(float4*)(g_Q + (size_t)node*64 + c8 + 4) = make_float4(aq[4],aq[5],aq[6],aq[7]);
        *(float4*)(g_K + (size_t)node*64 + c8)     = make_float4(ak[0],ak[1],ak[2],ak[3]);
        *(float4*)(g_K + (size_t)node*64 + c8 + 4) = make_float4(ak[4],ak[5],ak[6],ak[7]);
    }
    __syncthreads();
    // stash Q tile into hs (reuse) for U computation
    #pragma unroll
    for (int j = 0; j < 8; j++) hs[n0*64 + c8 + j] = aq[j];
    __syncthreads();
    if (valid) {
        int hh = c8 >> 4;
        float u[8];
        #pragma unroll
        for (int j = 0; j < 8; j++) {
            int c = c8 + j;
            float s = 0.f;
            #pragma unroll
            for (int cc = 0; cc < 16; cc++)
                s = fmaf(hs[n0*64 + 16*hh + cc], WEsT[(16*hh + cc)*16 + (c & 15)], s);
            u[j] = s;
        }
        *(float4*)(g_U + (size_t)node*64 + c8)     = make_float4(u[0],u[1],u[2],u[3]);
        *(float4*)(g_U + (size_t)node*64 + c8 + 4) = make_float4(u[4],u[5],u[6],u[7]);
    }
}

// ---------------- V,S fused, register-tiled ----------------
__global__ __launch_bounds__(256) void vs_kernel(const float* __restrict__ Wv, const float* __restrict__ bv,
                                                 const float* __restrict__ Ws, const float* __restrict__ bs) {
    __shared__ __align__(16) float hs[32*68];
    __shared__ __align__(16) float WVs[4096];
    __shared__ __align__(16) float WSs[4096];
    __shared__ float bVs[64], bSs[64];
    int t = threadIdx.x;
    for (int i = t; i < 4096; i += 256) { WVs[i] = Wv[i]; WSs[i] = Ws[i]; }
    if (t < 64) { bVs[t] = bv[t]; bSs[t] = bs[t]; }
    int base = blockIdx.x * 32;
    {
        int r = t >> 3, seg = t & 7;
        int node = base + r;
        const float* hp = g_h + (size_t)node*64 + seg*8;
        float4 a = make_float4(0,0,0,0), b = a;
        if (node < Nn) { a = *(const float4*)hp; b = *(const float4*)(hp + 4); }
        *(float4*)&hs[r*68 + seg*8]     = a;
        *(float4*)&hs[r*68 + seg*8 + 4] = b;
    }
    __syncthreads();
    int n0 = t >> 3;
    int c8 = (t & 7) * 8;
    float av[8], as_[8];
    #pragma unroll
    for (int j = 0; j < 8; j++) { av[j] = bVs[c8+j]; as_[j] = bSs[c8+j]; }
    #pragma unroll 4
    for (int k = 0; k < 64; k++) {
        float rh = hs[n0*68 + k];
        float4 v0 = *(float4*)&WVs[k*64 + c8];
        float4 v1 = *(float4*)&WVs[k*64 + c8 + 4];
        float4 s0 = *(float4*)&WSs[k*64 + c8];
        float4 s1 = *(float4*)&WSs[k*64 + c8 + 4];
        av[0]=fmaf(rh,v0.x,av[0]); av[1]=fmaf(rh,v0.y,av[1]); av[2]=fmaf(rh,v0.z,av[2]); av[3]=fmaf(rh,v0.w,av[3]);
        av[4]=fmaf(rh,v1.x,av[4]); av[5]=fmaf(rh,v1.y,av[5]); av[6]=fmaf(rh,v1.z,av[6]); av[7]=fmaf(rh,v1.w,av[7]);
        as_[0]=fmaf(rh,s0.x,as_[0]); as_[1]=fmaf(rh,s0.y,as_[1]); as_[2]=fmaf(rh,s0.z,as_[2]); as_[3]=fmaf(rh,s0.w,as_[3]);
        as_[4]=fmaf(rh,s1.x,as_[4]); as_[5]=fmaf(rh,s1.y,as_[5]); as_[6]=fmaf(rh,s1.z,as_[6]); as_[7]=fmaf(rh,s1.w,as_[7]);
    }
    int node = base + n0;
    if (node < Nn) {
        *(float4*)(g_V + (size_t)node*64 + c8)     = make_float4(av[0],av[1],av[2],av[3]);
        *(float4*)(g_V + (size_t)node*64 + c8 + 4) = make_float4(av[4],av[5],av[6],av[7]);
        *(float4*)(g_S + (size_t)node*64 + c8)     = make_float4(as_[0],as_[1],as_[2],as_[3]);
        *(float4*)(g_S + (size_t)node*64 + c8 + 4) = make_float4(as_[4],as_[5],as_[6],as_[7]);
    }
}

// ---------------- attention: warp per dst, online softmax, streamed edge data ----------------
__global__ __launch_bounds__(256) void attn_kernel(const float* __restrict__ Wel) {
    __shared__ float WEs[1024];
    for (int i = threadIdx.x; i < 1024; i += 256) WEs[i] = Wel[i];
    __syncthreads();

    int wid  = (blockIdx.x * blockDim.x + threadIdx.x) >> 5;
    int lane = threadIdx.x & 31;
    if (wid >= Nn) return;

    int hh = lane >> 3;
    int d2 = (lane & 7) * 2;

    float2 q = *(const float2*)(g_Q + (size_t)wid*64 + 2*lane);
    float2 u = *(const float2*)(g_U + (size_t)wid*64 + 2*lane);

    int beg = g_rowptr[wid], end = g_rowptr[wid + 1];
    float m = -INFINITY, dsum = 0.f;
    float avx = 0.f, avy = 0.f, awx = 0.f, awy = 0.f;

    int i = beg;
    for (; i + 4 <= end; i += 4) {
        int s0 = g_srcperm[i], s1 = g_srcperm[i+1], s2 = g_srcperm[i+2], s3 = g_srcperm[i+3];
        float2 K0 = *(const float2*)(g_K + (size_t)s0*64 + 2*lane);
        float2 K1 = *(const float2*)(g_K + (size_t)s1*64 + 2*lane);
        float2 K2 = *(const float2*)(g_K + (size_t)s2*64 + 2*lane);
        float2 K3 = *(const float2*)(g_K + (size_t)s3*64 + 2*lane);
        float2 V0 = *(const float2*)(g_V + (size_t)s0*64 + 2*lane);
        float2 V1 = *(const float2*)(g_V + (size_t)s1*64 + 2*lane);
        float2 V2 = *(const float2*)(g_V + (size_t)s2*64 + 2*lane);
        float2 V3 = *(const float2*)(g_V + (size_t)s3*64 + 2*lane);
        float2 E0 = *(const float2*)(g_eaperm + (size_t)(i+0)*16 + d2);
        float2 E1 = *(const float2*)(g_eaperm + (size_t)(i+1)*16 + d2);
        float2 E2 = *(const float2*)(g_eaperm + (size_t)(i+2)*16 + d2);
        float2 E3 = *(const float2*)(g_eaperm + (size_t)(i+3)*16 + d2);

        float t0 = q.x*K0.x + q.y*K0.y + u.x*E0.x + u.y*E0.y;
        float t1 = q.x*K1.x + q.y*K1.y + u.x*E1.x + u.y*E1.y;
        float t2 = q.x*K2.x + q.y*K2.y + u.x*E2.x + u.y*E2.y;
        float t3 = q.x*K3.x + q.y*K3.y + u.x*E3.x + u.y*E3.y;
        t0 += __shfl_xor_sync(0xffffffffu, t0, 1);
        t1 += __shfl_xor_sync(0xffffffffu, t1, 1);
        t2 += __shfl_xor_sync(0xffffffffu, t2, 1);
        t3 += __shfl_xor_sync(0xffffffffu, t3, 1);
        t0 += __shfl_xor_sync(0xffffffffu, t0, 2);
        t1 += __shfl_xor_sync(0xffffffffu, t1, 2);
        t2 += __shfl_xor_sync(0xffffffffu, t2, 2);
        t3 += __shfl_xor_sync(0xffffffffu, t3, 2);
        t0 += __shfl_xor_sync(0xffffffffu, t0, 4);
        t1 += __shfl_xor_sync(0xffffffffu, t1, 4);
        t2 += __shfl_xor_sync(0xffffffffu, t2, 4);
        t3 += __shfl_xor_sync(0xffffffffu, t3, 4);
        float a0 = t0*0.25f, a1 = t1*0.25f, a2 = t2*0.25f, a3 = t3*0.25f;

        float mn = fmaxf(fmaxf(fmaxf(a0, a1), fmaxf(a2, a3)), m);
        float corr = __expf(m - mn);
        float w0 = __expf(a0 - mn), w1 = __expf(a1 - mn);
        float w2 = __expf(a2 - mn), w3 = __expf(a3 - mn);
        dsum = dsum*corr + (w0 + w1) + (w2 + w3);
        avx = avx*corr + (w0*V0.x + w1*V1.x) + (w2*V2.x + w3*V3.x);
        avy = avy*corr + (w0*V0.y + w1*V1.y) + (w2*V2.y + w3*V3.y);
        awx = awx*corr + (w0*E0.x + w1*E1.x) + (w2*E2.x + w3*E3.x);
        awy = awy*corr + (w0*E0.y + w1*E1.y) + (w2*E2.y + w3*E3.y);
        m = mn;
    }
    for (; i < end; i++) {
        int s0 = g_srcperm[i];
        float2 K0 = *(const float2*)(g_K + (size_t)s0*64 + 2*lane);
        float2 V0 = *(const float2*)(g_V + (size_t)s0*64 + 2*lane);
        float2 E0 = *(const float2*)(g_eaperm + (size_t)i*16 + d2);
        float t0 = q.x*K0.x + q.y*K0.y + u.x*E0.x + u.y*E0.y;
        t0 += __shfl_xor_sync(0xffffffffu, t0, 1);
        t0 += __shfl_xor_sync(0xffffffffu, t0, 2);
        t0 += __shfl_xor_sync(0xffffffffu, t0, 4);
        float a0 = t0*0.25f;
        float mn = fmaxf(m, a0);
        float corr = __expf(m - mn);
        float w0 = __expf(a0 - mn);
        dsum = dsum*corr + w0;
        avx = avx*corr + w0*V0.x;
        avy = avy*corr + w0*V0.y;
        awx = awx*corr + w0*E0.x;
        awy = awy*corr + w0*E0.y;
        m = mn;
    }

    float ox = avx, oy = avy;
    #pragma unroll
    for (int jj = 0; jj < 8; jj++) {
        int srcl = (hh << 3) + jj;
        float bx = __shfl_sync(0xffffffffu, awx, srcl);
        float by = __shfl_sync(0xffffffffu, awy, srcl);
        ox = fmaf(bx, WEs[(2*jj)*64 + 2*lane],     ox);
        oy = fmaf(bx, WEs[(2*jj)*64 + 2*lane + 1], oy);
        ox = fmaf(by, WEs[(2*jj+1)*64 + 2*lane],     ox);
        oy = fmaf(by, WEs[(2*jj+1)*64 + 2*lane + 1], oy);
    }
    float inv = 1.f / (dsum + 1e-16f);
    float2 sv = *(const float2*)(g_S + (size_t)wid*64 + 2*lane);
    float o0 = fmaxf(fmaf(ox, inv, sv.x), 0.f);
    float o1 = fmaxf(fmaf(oy, inv, sv.y), 0.f);
    float2* hp = (float2*)(g_h + (size_t)wid*64 + 2*lane);
    float2 hv = *hp;
    hv.x += o0; hv.y += o1;
    *hp = hv;
}

// ---------------- pool: sorted-batch run-length accumulate ----------------
__global__ void pool_kernel(const int* __restrict__ batch) {
    int c = threadIdx.x & 63;
    int sub = threadIdx.x >> 6;
    int start = blockIdx.x * 1024 + sub * 256;
    if (start >= Nn) return;
    int end = min(start + 256, Nn);
    int gprev = batch[start];
    float acc = 0.f;
    int cnt = 0;
    for (int node = start; node < end; node++) {
        int g = batch[node];
        float v = g_h[(size_t)node*64 + c];
        if (g != gprev) {
            atomicAdd(&g_pool[gprev*64 + c], acc);
            if (c == 0) atomicAdd(&g_cnt[gprev], cnt);
            acc = 0.f; cnt = 0; gprev = g;
        }
        acc += v; cnt++;
    }
    atomicAdd(&g_pool[gprev*64 + c], acc);
    if (c == 0) atomicAdd(&g_cnt[gprev], cnt);
}

// ---------------- head MLP ----------------
__global__ void final_kernel(const float* __restrict__ W1, const float* __restrict__ b1,
                             const float* __restrict__ W2, const float* __restrict__ b2,
                             float* __restrict__ out) {
    int g = blockIdx.x;
    int j = threadIdx.x;
    float invc = 1.f / fmaxf((float)g_cnt[g], 1.f);
    float acc = b1[j];
    #pragma unroll
    for (int k = 0; k < 64; k++)
        acc = fmaf(g_pool[g*64 + k] * invc, W1[k*32 + j], acc);
    acc = fmaxf(acc, 0.f);
    float t = acc * W2[j];
    #pragma unroll
    for (int o = 16; o > 0; o >>= 1) t += __shfl_xor_sync(0xffffffffu, t, o);
    if (j == 0) out[g] = t + b2[0];
}

// ---------------- launch ----------------
extern "C" void kernel_launch(void* const* d_in, const int* in_sizes, int n_in,
                              void* d_out, int out_size) {
    const float* x     = (const float*)d_in[0];
    const int*   ei    = (const int*)  d_in[1];
    const float* eattr = (const float*)d_in[2];
    const int*   batch = (const int*)  d_in[3];
    const float* Wn = (const float*)d_in[4];  const float* bn = (const float*)d_in[5];
    const float* Wq = (const float*)d_in[6];  const float* bq = (const float*)d_in[7];
    const float* Wk = (const float*)d_in[8];  const float* bk = (const float*)d_in[9];
    const float* Wv = (const float*)d_in[10]; const float* bv = (const float*)d_in[11];
    const float* We = (const float*)d_in[12];
    const float* Ws = (const float*)d_in[13]; const float* bs = (const float*)d_in[14];
    const float* W1 = (const float*)d_in[15]; const float* b1 = (const float*)d_in[16];
    const float* W2 = (const float*)d_in[17]; const float* b2 = (const float*)d_in[18];
    float* out = (float*)d_out;

    const int* src = ei;
    const int* dst = ei + Ee;

    int nodeb = (Nn + 31) / 32;                   // 32-node tiles
    // order chosen so the profiler's fixed capture slot lands on qku_kernel
    node_in_kernel<<<nodeb, 256>>>(x, Wn, bn);    // 0
    zero_kernel<<<64, 256>>>();                   // 1
    hist_kernel<<<(Ee + 255)/256, 256>>>(dst);    // 2
    qku_kernel<<<nodeb, 256>>>(Wq, bq, Wk, bk, We);  // 3  (layer 0)
    scanA_kernel<<<NB, 1024>>>();                 // 4
    scanBC_kernel<<<NB, 1024>>>();                // 5
    scatter_kernel<<<(Ee + 255)/256, 256>>>(src, dst);   // 6
    gatherE_kernel<<<(Ee*4 + 255)/256, 256>>>(eattr);    // 7
    vs_kernel<<<nodeb, 256>>>(Wv, bv, Ws, bs);    // 8  (layer 0)
    attn_kernel<<<(Nn*32 + 255)/256, 256>>>(We);  // 9  (layer 0)

    for (int l = 1; l < 3; l++) {
        const float* Wql = Wq + (size_t)l*64*64; const float* bql = bq + (size_t)l*64;
        const float* Wkl = Wk + (size_t)l*64*64; const float* bkl = bk + (size_t)l*64;
        const float* Wvl = Wv + (size_t)l*64*64; const float* bvl = bv + (size_t)l*64;
        const float* Wsl = Ws + (size_t)l*64*64; const float* bsl = bs + (size_t)l*64;
        const float* Wel = We + (size_t)l*16*64;
        qku_kernel<<<nodeb, 256>>>(Wql, bql, Wkl, bkl, Wel);
        vs_kernel<<<nodeb, 256>>>(Wvl, bvl, Wsl, bsl);
        attn_kernel<<<(Nn*32 + 255)/256, 256>>>(Wel);
    }

    pool_kernel<<<(Nn + 1023)/1024, 256>>>(batch);
    final_kernel<<<Gg, 32>>>(W1, b1, W2, b2, out);
}

// round 11
// speedup vs baseline: 1.5398x; 1.5398x over previous
#include <cuda_runtime.h>
#include <math.h>

#define Nn 50000
#define Ee 1600000
#define Gg 64
#define NB 49   // ceil(Nn/1024)

// ---------------- device scratch ----------------
__device__ float g_h[Nn*64];
__device__ float g_Q[Nn*64];
__device__ float g_K[Nn*64];
__device__ float g_V[Nn*64];
__device__ float g_S[Nn*64];
__device__ int   g_deg[Nn];
__device__ int   g_rowptr[Nn+1];
__device__ int   g_cursor[Nn];
__device__ int   g_bsum[64];
__device__ int2  g_perm[Ee];
__device__ int   g_srcperm[Ee];
__device__ float g_eaperm[Ee*16];
__device__ float g_pool[Gg*64];
__device__ int   g_cnt[Gg];

// ---------------- f32x2 packed-FMA helpers ----------------
__device__ __forceinline__ unsigned long long pk2(float lo, float hi) {
    unsigned long long r;
    asm("mov.b64 %0,{%1,%2};" : "=l"(r) : "f"(lo), "f"(hi));
    return r;
}
__device__ __forceinline__ void fma2(unsigned long long& d, unsigned long long a, unsigned long long b) {
    asm("fma.rn.f32x2 %0,%1,%2,%0;" : "+l"(d) : "l"(a), "l"(b));
}
__device__ __forceinline__ float2 upk2(unsigned long long v) {
    float2 r;
    asm("mov.b64 {%0,%1},%2;" : "=f"(r.x), "=f"(r.y) : "l"(v));
    return r;
}

// ---------------- zero degree ----------------
__global__ void zero_kernel() {
    int i = blockIdx.x * blockDim.x + threadIdx.x;
    for (; i < Nn; i += gridDim.x * blockDim.x) g_deg[i] = 0;
}

// ---------------- degree histogram ----------------
__global__ void hist_kernel(const int* __restrict__ dst) {
    int e = blockIdx.x * blockDim.x + threadIdx.x;
    if (e < Ee) atomicAdd(&g_deg[dst[e]], 1);
}

// ---------------- scan A: block-local exclusive scan (+ zero pool) ----------------
__global__ void scanA_kernel() {
    __shared__ int sh[1024];
    int tid = threadIdx.x;
    int i = blockIdx.x * 1024 + tid;
    if (blockIdx.x == 0) {
        if (tid < Gg) g_cnt[tid] = 0;
        for (int j = tid; j < Gg*64; j += 1024) g_pool[j] = 0.f;
    }
    int v = (i < Nn) ? g_deg[i] : 0;
    sh[tid] = v;
    __syncthreads();
    for (int off = 1; off < 1024; off <<= 1) {
        int t = (tid >= off) ? sh[tid - off] : 0;
        __syncthreads();
        sh[tid] += t;
        __syncthreads();
    }
    if (i < Nn) g_rowptr[i] = sh[tid] - v;
    if (tid == 1023) g_bsum[blockIdx.x] = sh[1023];
}

// ---------------- scan B+C fused ----------------
__global__ void scanBC_kernel() {
    __shared__ int sh[64];
    __shared__ int carry;
    int t = threadIdx.x;
    if (t < 64) sh[t] = (t < blockIdx.x && t < NB) ? g_bsum[t] : 0;
    __syncthreads();
    if (t == 0) { int s = 0; for (int j = 0; j < 64; j++) s += sh[j]; carry = s; }
    __syncthreads();
    int i = blockIdx.x * 1024 + t;
    if (i < Nn) { int r = g_rowptr[i] + carry; g_rowptr[i] = r; g_cursor[i] = r; }
    if (i == 0) g_rowptr[Nn] = Ee;
}

// ---------------- scatter {src, edge id} into CSR(dst) order ----------------
__global__ void scatter_kernel(const int* __restrict__ src,
                               const int* __restrict__ dst) {
    int e = blockIdx.x * blockDim.x + threadIdx.x;
    if (e >= Ee) return;
    int d = dst[e];
    int p = atomicAdd(&g_cursor[d], 1);
    g_perm[p] = make_int2(src[e], e);
}

// ---------------- gather eattr into CSR order ----------------
__global__ void gatherE_kernel(const float* __restrict__ eattr) {
    int t = blockIdx.x * blockDim.x + threadIdx.x;
    if (t >= Ee * 4) return;
    int slot = t >> 2, part = t & 3;
    int2 p = g_perm[slot];
    float4 v = *(const float4*)(eattr + (size_t)p.y * 16 + part * 4);
    *(float4*)(g_eaperm + (size_t)slot * 16 + part * 4) = v;
    if (part == 0) g_srcperm[slot] = p.x;
}

// ---------------- input MLP: h = relu(x @ Wn + bn), 4-node reg tile, f32x2 ----------------
__global__ __launch_bounds__(256, 2) void node_in_kernel(const float* __restrict__ x,
                                                         const float* __restrict__ Wn,
                                                         const float* __restrict__ bn) {
    __shared__ __align__(16) float Ws[32*64];
    __shared__ float bs_[64];
    int t = threadIdx.x;
    for (int i = t; i < 32*64; i += 256) Ws[i] = Wn[i];
    if (t < 64) bs_[t] = bn[t];
    __syncthreads();

    int grp = t >> 3;
    int c8  = (t & 7) * 8;
    int node0 = blockIdx.x * 128 + grp * 4;
    const unsigned long long* W8 = (const unsigned long long*)Ws;

    unsigned long long acc[4][4];
    #pragma unroll
    for (int p = 0; p < 4; p++) {
        unsigned long long b = pk2(bs_[c8 + 2*p], bs_[c8 + 2*p + 1]);
        #pragma unroll
        for (int n = 0; n < 4; n++) acc[n][p] = b;
    }

    #pragma unroll 2
    for (int k4 = 0; k4 < 8; k4++) {
        float4 rh[4];
        #pragma unroll
        for (int n = 0; n < 4; n++) {
            int nd = node0 + n; if (nd > Nn - 1) nd = Nn - 1;
            rh[n] = *(const float4*)(x + (size_t)nd*32 + k4*4);
        }
        #pragma unroll
        for (int kk = 0; kk < 4; kk++) {
            int k = k4*4 + kk;
            unsigned long long w[4];
            int off = (k*64 + c8) >> 1;
            #pragma unroll
            for (int p = 0; p < 4; p++) w[p] = W8[off + p];
            #pragma unroll
            for (int n = 0; n < 4; n++) {
                float rv = ((const float*)&rh[n])[kk];
                unsigned long long r2 = pk2(rv, rv);
                #pragma unroll
                for (int p = 0; p < 4; p++) fma2(acc[n][p], r2, w[p]);
            }
        }
    }
    #pragma unroll
    for (int n = 0; n < 4; n++) {
        int nd = node0 + n;
        if (nd < Nn) {
            float2 x0 = upk2(acc[n][0]), x1 = upk2(acc[n][1]);
            float2 x2 = upk2(acc[n][2]), x3 = upk2(acc[n][3]);
            float4 o0 = make_float4(fmaxf(x0.x,0.f), fmaxf(x0.y,0.f), fmaxf(x1.x,0.f), fmaxf(x1.y,0.f));
            float4 o1 = make_float4(fmaxf(x2.x,0.f), fmaxf(x2.y,0.f), fmaxf(x3.x,0.f), fmaxf(x3.y,0.f));
            *(float4*)(g_h + (size_t)nd*64 + c8)     = o0;
            *(float4*)(g_h + (size_t)nd*64 + c8 + 4) = o1;
        }
    }
}

// ---------------- dual 64x64 GEMM from g_h: sel 0 -> (Q,K), sel 1 -> (V,S) ----------------
__global__ __launch_bounds__(256, 2) void gemm2_kernel(const float* __restrict__ WA,
                                                       const float* __restrict__ bA,
                                                       const float* __restrict__ WB,
                                                       const float* __restrict__ bB,
                                                       int sel) {
    __shared__ __align__(16) float WAs[4096];
    __shared__ __align__(16) float WBs[4096];
    __shared__ float bAs[64], bBs[64];
    int t = threadIdx.x;
    for (int i = t; i < 4096; i += 256) { WAs[i] = WA[i]; WBs[i] = WB[i]; }
    if (t < 64) { bAs[t] = bA[t]; bBs[t] = bB[t]; }
    __syncthreads();

    int grp = t >> 3;
    int c8  = (t & 7) * 8;
    int node0 = blockIdx.x * 128 + grp * 4;
    const unsigned long long* WA8 = (const unsigned long long*)WAs;
    const unsigned long long* WB8 = (const unsigned long long*)WBs;

    unsigned long long accA[4][4], accB[4][4];
    #pragma unroll
    for (int p = 0; p < 4; p++) {
        unsigned long long ba = pk2(bAs[c8 + 2*p], bAs[c8 + 2*p + 1]);
        unsigned long long bb = pk2(bBs[c8 + 2*p], bBs[c8 + 2*p + 1]);
        #pragma unroll
        for (int n = 0; n < 4; n++) { accA[n][p] = ba; accB[n][p] = bb; }
    }

    #pragma unroll 2
    for (int k4 = 0; k4 < 16; k4++) {
        float4 rh[4];
        #pragma unroll
        for (int n = 0; n < 4; n++) {
            int nd = node0 + n; if (nd > Nn - 1) nd = Nn - 1;
            rh[n] = *(const float4*)(g_h + (size_t)nd*64 + k4*4);
        }
        #pragma unroll
        for (int kk = 0; kk < 4; kk++) {
            int k = k4*4 + kk;
            unsigned long long wa[4], wb[4];
            int off = (k*64 + c8) >> 1;
            #pragma unroll
            for (int p = 0; p < 4; p++) { wa[p] = WA8[off + p]; wb[p] = WB8[off + p]; }
            #pragma unroll
            for (int n = 0; n < 4; n++) {
                float rv = ((const float*)&rh[n])[kk];
                unsigned long long r2 = pk2(rv, rv);
                #pragma unroll
                for (int p = 0; p < 4; p++) { fma2(accA[n][p], r2, wa[p]); fma2(accB[n][p], r2, wb[p]); }
            }
        }
    }

    float* OA = sel ? g_V : g_Q;
    float* OB = sel ? g_S : g_K;
    #pragma unroll
    for (int n = 0; n < 4; n++) {
        int nd = node0 + n;
        if (nd < Nn) {
            float2 a0 = upk2(accA[n][0]), a1 = upk2(accA[n][1]);
            float2 a2 = upk2(accA[n][2]), a3 = upk2(accA[n][3]);
            float2 b0 = upk2(accB[n][0]), b1 = upk2(accB[n][1]);
            float2 b2 = upk2(accB[n][2]), b3 = upk2(accB[n][3]);
            *(float4*)(OA + (size_t)nd*64 + c8)     = make_float4(a0.x, a0.y, a1.x, a1.y);
            *(float4*)(OA + (size_t)nd*64 + c8 + 4) = make_float4(a2.x, a2.y, a3.x, a3.y);
            *(float4*)(OB + (size_t)nd*64 + c8)     = make_float4(b0.x, b0.y, b1.x, b1.y);
            *(float4*)(OB + (size_t)nd*64 + c8 + 4) = make_float4(b2.x, b2.y, b3.x, b3.y);
        }
    }
}

// ---------------- attention: warp per dst, online softmax, u computed inline ----------------
__global__ __launch_bounds__(256) void attn_kernel(const float* __restrict__ Wel) {
    __shared__ float WEs[1024];    // We[j*64 + c]
    __shared__ float WEsT[1024];   // WEsT[ch*16 + j] = We[j][ch]
    for (int i = threadIdx.x; i < 1024; i += 256) {
        WEs[i] = Wel[i];
        int ch = i >> 4, j = i & 15;
        WEsT[i] = Wel[j*64 + ch];
    }
    __syncthreads();

    int wid  = (blockIdx.x * blockDim.x + threadIdx.x) >> 5;
    int lane = threadIdx.x & 31;
    if (wid >= Nn) return;

    int hh = lane >> 3;
    int d2 = (lane & 7) * 2;

    float2 q = *(const float2*)(g_Q + (size_t)wid*64 + 2*lane);

    // u[h][d2], u[h][d2+1] = sum_cc q[h][cc] * We^T — 16 shuffles, once per node
    float ux = 0.f, uy = 0.f;
    #pragma unroll
    for (int cc = 0; cc < 16; cc++) {
        float qv = __shfl_sync(0xffffffffu, (cc & 1) ? q.y : q.x, (hh << 3) + (cc >> 1));
        ux = fmaf(qv, WEsT[((hh << 4) + cc)*16 + d2],     ux);
        uy = fmaf(qv, WEsT[((hh << 4) + cc)*16 + d2 + 1], uy);
    }
    float2 u = make_float2(ux, uy);

    int beg = g_rowptr[wid], end = g_rowptr[wid + 1];
    float m = -INFINITY, dsum = 0.f;
    float avx = 0.f, avy = 0.f, awx = 0.f, awy = 0.f;

    int i = beg;
    for (; i + 4 <= end; i += 4) {
        int s0 = g_srcperm[i], s1 = g_srcperm[i+1], s2 = g_srcperm[i+2], s3 = g_srcperm[i+3];
        float2 K0 = *(const float2*)(g_K + (size_t)s0*64 + 2*lane);
        float2 K1 = *(const float2*)(g_K + (size_t)s1*64 + 2*lane);
        float2 K2 = *(const float2*)(g_K + (size_t)s2*64 + 2*lane);
        float2 K3 = *(const float2*)(g_K + (size_t)s3*64 + 2*lane);
        float2 V0 = *(const float2*)(g_V + (size_t)s0*64 + 2*lane);
        float2 V1 = *(const float2*)(g_V + (size_t)s1*64 + 2*lane);
        float2 V2 = *(const float2*)(g_V + (size_t)s2*64 + 2*lane);
        float2 V3 = *(const float2*)(g_V + (size_t)s3*64 + 2*lane);
        float2 E0 = *(const float2*)(g_eaperm + (size_t)(i+0)*16 + d2);
        float2 E1 = *(const float2*)(g_eaperm + (size_t)(i+1)*16 + d2);
        float2 E2 = *(const float2*)(g_eaperm + (size_t)(i+2)*16 + d2);
        float2 E3 = *(const float2*)(g_eaperm + (size_t)(i+3)*16 + d2);

        float t0 = q.x*K0.x + q.y*K0.y + u.x*E0.x + u.y*E0.y;
        float t1 = q.x*K1.x + q.y*K1.y + u.x*E1.x + u.y*E1.y;
        float t2 = q.x*K2.x + q.y*K2.y + u.x*E2.x + u.y*E2.y;
        float t3 = q.x*K3.x + q.y*K3.y + u.x*E3.x + u.y*E3.y;
        t0 += __shfl_xor_sync(0xffffffffu, t0, 1);
        t1 += __shfl_xor_sync(0xffffffffu, t1, 1);
        t2 += __shfl_xor_sync(0xffffffffu, t2, 1);
        t3 += __shfl_xor_sync(0xffffffffu, t3, 1);
        t0 += __shfl_xor_sync(0xffffffffu, t0, 2);
        t1 += __shfl_xor_sync(0xffffffffu, t1, 2);
        t2 += __shfl_xor_sync(0xffffffffu, t2, 2);
        t3 += __shfl_xor_sync(0xffffffffu, t3, 2);
        t0 += __shfl_xor_sync(0xffffffffu, t0, 4);
        t1 += __shfl_xor_sync(0xffffffffu, t1, 4);
        t2 += __shfl_xor_sync(0xffffffffu, t2, 4);
        t3 += __shfl_xor_sync(0xffffffffu, t3, 4);
        float a0 = t0*0.25f, a1 = t1*0.25f, a2 = t2*0.25f, a3 = t3*0.25f;

        float mn = fmaxf(fmaxf(fmaxf(a0, a1), fmaxf(a2, a3)), m);
        float corr = __expf(m - mn);
        float w0 = __expf(a0 - mn), w1 = __expf(a1 - mn);
        float w2 = __expf(a2 - mn), w3 = __expf(a3 - mn);
        dsum = dsum*corr + (w0 + w1) + (w2 + w3);
        avx = avx*corr + (w0*V0.x + w1*V1.x) + (w2*V2.x + w3*V3.x);
        avy = avy*corr + (w0*V0.y + w1*V1.y) + (w2*V2.y + w3*V3.y);
        awx = awx*corr + (w0*E0.x + w1*E1.x) + (w2*E2.x + w3*E3.x);
        awy = awy*corr + (w0*E0.y + w1*E1.y) + (w2*E2.y + w3*E3.y);
        m = mn;
    }
    for (; i < end; i++) {
        int s0 = g_srcperm[i];
        float2 K0 = *(const float2*)(g_K + (size_t)s0*64 + 2*lane);
        float2 V0 = *(const float2*)(g_V + (size_t)s0*64 + 2*lane);
        float2 E0 = *(const float2*)(g_eaperm + (size_t)i*16 + d2);
        float t0 = q.x*K0.x + q.y*K0.y + u.x*E0.x + u.y*E0.y;
        t0 += __shfl_xor_sync(0xffffffffu, t0, 1);
        t0 += __shfl_xor_sync(0xffffffffu, t0, 2);
        t0 += __shfl_xor_sync(0xffffffffu, t0, 4);
        float a0 = t0*0.25f;
        float mn = fmaxf(m, a0);
        float corr = __expf(m - mn);
        float w0 = __expf(a0 - mn);
        dsum = dsum*corr + w0;
        avx = avx*corr + w0*V0.x;
        avy = avy*corr + w0*V0.y;
        awx = awx*corr + w0*E0.x;
        awy = awy*corr + w0*E0.y;
        m = mn;
    }

    float ox = avx, oy = avy;
    #pragma unroll
    for (int jj = 0; jj < 8; jj++) {
        int srcl = (hh << 3) + jj;
        float bx = __shfl_sync(0xffffffffu, awx, srcl);
        float by = __shfl_sync(0xffffffffu, awy, srcl);
        ox = fmaf(bx, WEs[(2*jj)*64 + 2*lane],       ox);
        oy = fmaf(bx, WEs[(2*jj)*64 + 2*lane + 1],   oy);
        ox = fmaf(by, WEs[(2*jj+1)*64 + 2*lane],     ox);
        oy = fmaf(by, WEs[(2*jj+1)*64 + 2*lane + 1], oy);
    }
    float inv = 1.f / (dsum + 1e-16f);
    float2 sv = *(const float2*)(g_S + (size_t)wid*64 + 2*lane);
    float o0 = fmaxf(fmaf(ox, inv, sv.x), 0.f);
    float o1 = fmaxf(fmaf(oy, inv, sv.y), 0.f);
    float2* hp = (float2*)(g_h + (size_t)wid*64 + 2*lane);
    float2 hv = *hp;
    hv.x += o0; hv.y += o1;
    *hp = hv;
}

// ---------------- pool: sorted-batch run-length accumulate ----------------
__global__ void pool_kernel(const int* __restrict__ batch) {
    int c = threadIdx.x & 63;
    int sub = threadIdx.x >> 6;
    int start = blockIdx.x * 1024 + sub * 256;
    if (start >= Nn) return;
    int end = min(start + 256, Nn);
    int gprev = batch[start];
    float acc = 0.f;
    int cnt = 0;
    for (int node = start; node < end; node++) {
        int g = batch[node];
        float v = g_h[(size_t)node*64 + c];
        if (g != gprev) {
            atomicAdd(&g_pool[gprev*64 + c], acc);
            if (c == 0) atomicAdd(&g_cnt[gprev], cnt);
            acc = 0.f; cnt = 0; gprev = g;
        }
        acc += v; cnt++;
    }
    atomicAdd(&g_pool[gprev*64 + c], acc);
    if (c == 0) atomicAdd(&g_cnt[gprev], cnt);
}

// ---------------- head MLP ----------------
__global__ void final_kernel(const float* __restrict__ W1, const float* __restrict__ b1,
                             const float* __restrict__ W2, const float* __restrict__ b2,
                             float* __restrict__ out) {
    int g = blockIdx.x;
    int j = threadIdx.x;
    float invc = 1.f / fmaxf((float)g_cnt[g], 1.f);
    float acc = b1[j];
    #pragma unroll
    for (int k = 0; k < 64; k++)
        acc = fmaf(g_pool[g*64 + k] * invc, W1[k*32 + j], acc);
    acc = fmaxf(acc, 0.f);
    float t = acc * W2[j];
    #pragma unroll
    for (int o = 16; o > 0; o >>= 1) t += __shfl_xor_sync(0xffffffffu, t, o);
    if (j == 0) out[g] = t + b2[0];
}

// ---------------- launch ----------------
extern "C" void kernel_launch(void* const* d_in, const int* in_sizes, int n_in,
                              void* d_out, int out_size) {
    const float* x     = (const float*)d_in[0];
    const int*   ei    = (const int*)  d_in[1];
    const float* eattr = (const float*)d_in[2];
    const int*   batch = (const int*)  d_in[3];
    const float* Wn = (const float*)d_in[4];  const float* bn = (const float*)d_in[5];
    const float* Wq = (const float*)d_in[6];  const float* bq = (const float*)d_in[7];
    const float* Wk = (const float*)d_in[8];  const float* bk = (const float*)d_in[9];
    const float* Wv = (const float*)d_in[10]; const float* bv = (const float*)d_in[11];
    const float* We = (const float*)d_in[12];
    const float* Ws = (const float*)d_in[13]; const float* bs = (const float*)d_in[14];
    const float* W1 = (const float*)d_in[15]; const float* b1 = (const float*)d_in[16];
    const float* W2 = (const float*)d_in[17]; const float* b2 = (const float*)d_in[18];
    float* out = (float*)d_out;

    const int* src = ei;
    const int* dst = ei + Ee;

    int gemmb = (Nn + 127) / 128;
    // order: capture slot #3 lands on gemm2_kernel (Q,K layer 0)
    node_in_kernel<<<gemmb, 256>>>(x, Wn, bn);                  // 0
    zero_kernel<<<64, 256>>>();                                 // 1
    hist_kernel<<<(Ee + 255)/256, 256>>>(dst);                  // 2
    gemm2_kernel<<<gemmb, 256>>>(Wq, bq, Wk, bk, 0);            // 3
    scanA_kernel<<<NB, 1024>>>();                               // 4
    scanBC_kernel<<<NB, 1024>>>();                              // 5
    scatter_kernel<<<(Ee + 255)/256, 256>>>(src, dst);          // 6
    gatherE_kernel<<<(Ee*4 + 255)/256, 256>>>(eattr);           // 7
    gemm2_kernel<<<gemmb, 256>>>(Wv, bv, Ws, bs, 1);            // 8
    attn_kernel<<<(Nn*32 + 255)/256, 256>>>(We);                // 9

    for (int l = 1; l < 3; l++) {
        const float* Wql = Wq + (size_t)l*64*64; const float* bql = bq + (size_t)l*64;
        const float* Wkl = Wk + (size_t)l*64*64; const float* bkl = bk + (size_t)l*64;
        const float* Wvl = Wv + (size_t)l*64*64; const float* bvl = bv + (size_t)l*64;
        const float* Wsl = Ws + (size_t)l*64*64; const float* bsl = bs + (size_t)l*64;
        const float* Wel = We + (size_t)l*16*64;
        gemm2_kernel<<<gemmb, 256>>>(Wql, bql, Wkl, bkl, 0);
        gemm2_kernel<<<gemmb, 256>>>(Wvl, bvl, Wsl, bsl, 1);
        attn_kernel<<<(Nn*32 + 255)/256, 256>>>(Wel);
    }

    pool_kernel<<<(Nn + 1023)/1024, 256>>>(batch);
    final_kernel<<<Gg, 32>>>(W1, b1, W2, b2, out);
}